// round 15
// baseline (speedup 1.0000x reference)
#include <cuda_runtime.h>

#define NN 100000
#define NE 1250000
#define HID 64
#define NG 256
#define NC 10
#define TR 64            // rows per GEMM block
#define GEMM_T 256       // threads per GEMM block
#define NBLK 391         // ceil(NN/256)
#define HCHUNK 35008     // pipeline split point (multiple of TR; ~0.35*NN)

typedef unsigned long long ull;

// ---------------- scratch (static device globals; zero-initialized at load) -------
__device__ int   g_cnt_in[NN];        // in-degree; ZERO at entry, re-zeroed by rowstart
__device__ int   g_fill[NN];          // CSR fill cursors (zeroed by rowstart pre-fill)
__device__ int   g_rowstart[NN + 1];  // CSR row offsets
__device__ float g_dinv[NN];          // 1/sqrt(deg+1)
__device__ int   g_bsum[NBLK];        // per-block degree sums
__device__ int2  g_csr[NE];           // (src, bitcast(norm)) per edge, grouped by dst
__device__ float g_buf0[NN * HID];    // layer buffers (ping-pong)
__device__ float g_buf1[NN * HID];
__device__ float g_pool[NG * HID];    // per-graph feature sums
__device__ float g_gcnt[NG];          // per-graph node counts

__device__ __forceinline__ float* buf_sel(int which) {
    return (which == 0) ? g_buf0 : g_buf1;
}
__device__ __forceinline__ const float* cbuf_sel(int which) {
    return (which == 0) ? g_buf0 : g_buf1;
}

// Per-warp int64-vs-int32 detection from edge_index (random values; if stored as
// little-endian int64 < 2^31, every odd 32-bit word is 0). One load + ballot.
__device__ __forceinline__ int detect64(const int* __restrict__ ei32) {
    int lane = threadIdx.x & 31;
    int w = ei32[1 + 2 * lane];       // odd words 1..63
    return __all_sync(0xffffffffu, w == 0);
}

__device__ __forceinline__ int ld_idx(const void* p, long long e, int is64) {
    if (is64) return (int)((const long long*)p)[e];
    return ((const int*)p)[e];
}

// packed f32x2 helpers (FFMA2 — ptxas never emits this from C++)
__device__ __forceinline__ ull ffma2(ull a, ull b, ull c) {
    ull d;
    asm("fma.rn.f32x2 %0, %1, %2, %3;" : "=l"(d) : "l"(a), "l"(b), "l"(c));
    return d;
}
__device__ __forceinline__ ull bcast2(float x) {
    ull d;
    asm("mov.b64 %0, {%1, %1};" : "=l"(d) : "f"(x));
    return d;
}

// ---------------- CSR gather for one destination row, 16 threads/row --------------
__device__ __forceinline__ float4 gather_row(const float* __restrict__ in, int i, int c)
{
    int beg = g_rowstart[i];
    int end = g_rowstart[i + 1];
    float di = g_dinv[i];
    float sw = di * di;

    float4 v = *(const float4*)&in[i * 64 + c];
    float4 s0 = make_float4(v.x * sw, v.y * sw, v.z * sw, v.w * sw);
    float4 s1 = make_float4(0.f, 0.f, 0.f, 0.f);

    int e = beg;
    for (; e + 3 < end; e += 4) {
        int2 p0 = g_csr[e];
        int2 p1 = g_csr[e + 1];
        int2 p2 = g_csr[e + 2];
        int2 p3 = g_csr[e + 3];
        float w0 = __int_as_float(p0.y), w1 = __int_as_float(p1.y);
        float w2 = __int_as_float(p2.y), w3 = __int_as_float(p3.y);
        float4 v0 = *(const float4*)&in[p0.x * 64 + c];
        float4 v1 = *(const float4*)&in[p1.x * 64 + c];
        float4 v2 = *(const float4*)&in[p2.x * 64 + c];
        float4 v3 = *(const float4*)&in[p3.x * 64 + c];
        s0.x += v0.x * w0 + v1.x * w1;  s1.x += v2.x * w2 + v3.x * w3;
        s0.y += v0.y * w0 + v1.y * w1;  s1.y += v2.y * w2 + v3.y * w3;
        s0.z += v0.z * w0 + v1.z * w1;  s1.z += v2.z * w2 + v3.z * w3;
        s0.w += v0.w * w0 + v1.w * w1;  s1.w += v2.w * w2 + v3.w * w3;
    }
    for (; e < end; e++) {
        int2 p0 = g_csr[e];
        float w0 = __int_as_float(p0.y);
        float4 v0 = *(const float4*)&in[p0.x * 64 + c];
        s0.x += v0.x * w0; s0.y += v0.y * w0; s0.z += v0.z * w0; s0.w += v0.w * w0;
    }
    return make_float4(s0.x + s1.x, s0.y + s1.y, s0.z + s1.z, s0.w + s1.w);
}

// Same, but applies relu(row + bias4) to every loaded row first (commutation fold
// of the old layer-3 GEMM operand transform: A_hat relu(h2+b2)).
__device__ __forceinline__ float4 gather_row_relu(const float* __restrict__ in,
                                                  int i, int c, float4 bv)
{
    int beg = g_rowstart[i];
    int end = g_rowstart[i + 1];
    float di = g_dinv[i];
    float sw = di * di;

    float4 v = *(const float4*)&in[i * 64 + c];
    v.x = fmaxf(v.x + bv.x, 0.f); v.y = fmaxf(v.y + bv.y, 0.f);
    v.z = fmaxf(v.z + bv.z, 0.f); v.w = fmaxf(v.w + bv.w, 0.f);
    float4 s0 = make_float4(v.x * sw, v.y * sw, v.z * sw, v.w * sw);

    int e = beg;
    for (; e + 1 < end; e += 2) {
        int2 p0 = g_csr[e];
        int2 p1 = g_csr[e + 1];
        float w0 = __int_as_float(p0.y), w1 = __int_as_float(p1.y);
        float4 v0 = *(const float4*)&in[p0.x * 64 + c];
        float4 v1 = *(const float4*)&in[p1.x * 64 + c];
        v0.x = fmaxf(v0.x + bv.x, 0.f); v0.y = fmaxf(v0.y + bv.y, 0.f);
        v0.z = fmaxf(v0.z + bv.z, 0.f); v0.w = fmaxf(v0.w + bv.w, 0.f);
        v1.x = fmaxf(v1.x + bv.x, 0.f); v1.y = fmaxf(v1.y + bv.y, 0.f);
        v1.z = fmaxf(v1.z + bv.z, 0.f); v1.w = fmaxf(v1.w + bv.w, 0.f);
        s0.x += v0.x * w0 + v1.x * w1;
        s0.y += v0.y * w0 + v1.y * w1;
        s0.z += v0.z * w0 + v1.z * w1;
        s0.w += v0.w * w0 + v1.w * w1;
    }
    if (e < end) {
        int2 p0 = g_csr[e];
        float w0 = __int_as_float(p0.y);
        float4 v0 = *(const float4*)&in[p0.x * 64 + c];
        v0.x = fmaxf(v0.x + bv.x, 0.f); v0.y = fmaxf(v0.y + bv.y, 0.f);
        v0.z = fmaxf(v0.z + bv.z, 0.f); v0.w = fmaxf(v0.w + bv.w, 0.f);
        s0.x += v0.x * w0; s0.y += v0.y * w0; s0.z += v0.z * w0; s0.w += v0.w * w0;
    }
    return s0;
}

// ---------------- preprocessing ----------------
__global__ void count_kernel(const void* __restrict__ ei) {
    int is64 = detect64((const int*)ei);
    int e = blockIdx.x * blockDim.x + threadIdx.x;
    if (e >= NE) return;
    atomicAdd(&g_cnt_in[ld_idx(ei, (long long)NE + e, is64)], 1);
}

// per-block degree sums (+dinv fused)
__global__ void blocksum_kernel() {
    __shared__ int sred[256];
    int i = blockIdx.x * 256 + threadIdx.x;
    int v = (i < NN) ? g_cnt_in[i] : 0;
    if (i < NN) g_dinv[i] = rsqrtf((float)v + 1.0f);
    sred[threadIdx.x] = v;
    __syncthreads();
    for (int h = 128; h > 0; h >>= 1) {
        if (threadIdx.x < h) sred[threadIdx.x] += sred[threadIdx.x + h];
        __syncthreads();
    }
    if (threadIdx.x == 0) g_bsum[blockIdx.x] = sred[0];
}

// rowstart: inline prefix over g_bsum + block-local scan; resets cnt/fill for reuse
__global__ void rowstart_kernel() {
    __shared__ int s[256];
    int t = threadIdx.x;

    int pre = 0;
    for (int j = t; j < blockIdx.x; j += 256) pre += g_bsum[j];
    s[t] = pre;
    __syncthreads();
    for (int h = 128; h > 0; h >>= 1) {
        if (t < h) s[t] += s[t + h];
        __syncthreads();
    }
    int base = s[0];
    __syncthreads();

    int i = blockIdx.x * 256 + t;
    int own = (i < NN) ? g_cnt_in[i] : 0;
    s[t] = own;
    __syncthreads();
    for (int off = 1; off < 256; off <<= 1) {
        int v = (t >= off) ? s[t - off] : 0;
        __syncthreads();
        s[t] += v;
        __syncthreads();
    }
    if (i < NN) {
        g_rowstart[i] = base + s[t] - own;
        g_fill[i] = 0;
        g_cnt_in[i] = 0;   // consume-and-reset for next call (deterministic)
    }
    if (i == 0) g_rowstart[NN] = NE;
}

__global__ void fill_kernel(const void* __restrict__ ei) {
    int is64 = detect64((const int*)ei);
    int e = blockIdx.x * blockDim.x + threadIdx.x;
    if (e >= NE) return;
    int s = ld_idx(ei, e, is64);
    int d = ld_idx(ei, (long long)NE + e, is64);
    int pos = g_rowstart[d] + atomicAdd(&g_fill[d], 1);
    float w = g_dinv[s] * g_dinv[d];
    g_csr[pos] = make_int2(s, __float_as_int(w));
}

// ---------------- GEMM: out_sel = act(in (+bias)) @ W, rows [row_base, row_end) ---
__global__ void __launch_bounds__(GEMM_T, 5) gemm_kernel(
    const float* __restrict__ in_ext, int in_sel,
    const float* __restrict__ bias,
    const float* __restrict__ W, int out_sel, int row_base, int row_end)
{
    __shared__ float sIn[TR * 68];     // [r][k], stride 68
    __shared__ float sW[64 * 64];      // deswizzled: [k][(j4&1)*32 + (j4>>1)*4 + t]

    const float* in = in_ext ? in_ext : cbuf_sel(in_sel);
    float* out = buf_sel(out_sel);

    int tid = threadIdx.x;
    int r0 = row_base + blockIdx.x * TR;
    const bool has_bias = (bias != nullptr);

    for (int q = tid; q < 64 * 16; q += GEMM_T) {
        int kk = q >> 4, j4 = q & 15;
        float4 w = *(const float4*)&W[kk * 64 + j4 * 4];
        *(float4*)&sW[kk * 64 + (j4 & 1) * 32 + (j4 >> 1) * 4] = w;
    }
    for (int q = tid; q < TR * 16; q += GEMM_T) {
        int r = q >> 4, k4 = q & 15;
        int gr = r0 + r;
        float4 v = make_float4(0.f, 0.f, 0.f, 0.f);
        if (gr < row_end) {
            v = *(const float4*)&in[gr * 64 + k4 * 4];
            if (has_bias) {
                v.x = fmaxf(v.x + bias[k4 * 4 + 0], 0.f);
                v.y = fmaxf(v.y + bias[k4 * 4 + 1], 0.f);
                v.z = fmaxf(v.z + bias[k4 * 4 + 2], 0.f);
                v.w = fmaxf(v.w + bias[k4 * 4 + 3], 0.f);
            }
        }
        *(float4*)&sIn[r * 68 + k4 * 4] = v;
    }
    __syncthreads();

    const int cx = tid & 7;
    const int ry2 = (tid >> 3) * 2;

    ull acc[2][4] = {};

    #pragma unroll 2
    for (int k0 = 0; k0 < 64; k0 += 4) {
        float4 a0 = *(const float4*)&sIn[(ry2 + 0) * 68 + k0];
        float4 a1 = *(const float4*)&sIn[(ry2 + 1) * 68 + k0];
        float a0v[4] = {a0.x, a0.y, a0.z, a0.w};
        float a1v[4] = {a1.x, a1.y, a1.z, a1.w};
        #pragma unroll
        for (int kk = 0; kk < 4; kk++) {
            const float* wrow = &sW[(k0 + kk) * 64];
            ulonglong2 wa = *(const ulonglong2*)&wrow[cx * 4];
            ulonglong2 wb = *(const ulonglong2*)&wrow[32 + cx * 4];
            ull x0 = bcast2(a0v[kk]);
            ull x1 = bcast2(a1v[kk]);
            acc[0][0] = ffma2(x0, wa.x, acc[0][0]);
            acc[0][1] = ffma2(x0, wa.y, acc[0][1]);
            acc[0][2] = ffma2(x0, wb.x, acc[0][2]);
            acc[0][3] = ffma2(x0, wb.y, acc[0][3]);
            acc[1][0] = ffma2(x1, wa.x, acc[1][0]);
            acc[1][1] = ffma2(x1, wa.y, acc[1][1]);
            acc[1][2] = ffma2(x1, wb.x, acc[1][2]);
            acc[1][3] = ffma2(x1, wb.y, acc[1][3]);
        }
    }

    #pragma unroll
    for (int i = 0; i < 2; i++) {
        int gr = r0 + ry2 + i;
        if (gr < row_end) {
            union { ull u[4]; float4 f[2]; } row;
            row.u[0] = acc[i][0]; row.u[1] = acc[i][1];
            row.u[2] = acc[i][2]; row.u[3] = acc[i][3];
            *(float4*)&out[gr * 64 + cx * 8]     = row.f[0];
            *(float4*)&out[gr * 64 + cx * 8 + 4] = row.f[1];
        }
    }
}

// ---------------- standalone gather over node range [node_base, node_end) ---------
__global__ void __launch_bounds__(256) gather_kernel(int in_sel, int out_sel,
                                                     int node_base, int node_end)
{
    const float* in = cbuf_sel(in_sel);
    float* acc_out = buf_sel(out_sel);

    int t = blockIdx.x * blockDim.x + threadIdx.x;
    int i = node_base + (t >> 4);
    if (i >= node_end) return;
    int c = (t & 15) << 2;

    float4 s = gather_row(in, i, c);
    *(float4*)&acc_out[i * 64 + c] = s;
}

// ---------------- gather of relu(in + b): out = A_hat relu(in + b) ----------------
__global__ void __launch_bounds__(256) gather_relu_kernel(
    int in_sel, int out_sel, const float* __restrict__ bias)
{
    const float* in = cbuf_sel(in_sel);
    float* acc_out = buf_sel(out_sel);

    int t = blockIdx.x * blockDim.x + threadIdx.x;
    int i = t >> 4;
    if (i >= NN) return;
    int c = (t & 15) << 2;
    float4 bv = *(const float4*)&bias[c];

    float4 s = gather_row_relu(in, i, c, bv);
    *(float4*)&acc_out[i * 64 + c] = s;
}

// ---------------- segmented mean pool (batch is sorted; no atomics) ----------------
__global__ void __launch_bounds__(256) pool_kernel(
    int in_sel, const void* __restrict__ batch, const int* __restrict__ ei32)
{
    __shared__ float4 sP[16][16];
    const float* acc = cbuf_sel(in_sel);
    int is64 = detect64(ei32);
    int g = blockIdx.x;
    int tid = threadIdx.x;
    int chunk = tid >> 4;
    int c4 = tid & 15;

    int lo = 0, hi = NN;
    while (lo < hi) { int mid = (lo + hi) >> 1; if (ld_idx(batch, mid, is64) < g) lo = mid + 1; else hi = mid; }
    int start = lo;
    lo = start; hi = NN;
    while (lo < hi) { int mid = (lo + hi) >> 1; if (ld_idx(batch, mid, is64) < g + 1) lo = mid + 1; else hi = mid; }
    int end = lo;

    float4 sum = make_float4(0.f, 0.f, 0.f, 0.f);
    for (int n = start + chunk; n < end; n += 16) {
        float4 v = *(const float4*)&acc[n * 64 + c4 * 4];
        sum.x += v.x; sum.y += v.y; sum.z += v.z; sum.w += v.w;
    }
    sP[chunk][c4] = sum;
    __syncthreads();
    for (int h = 8; h > 0; h >>= 1) {
        if (chunk < h) {
            float4 a = sP[chunk][c4], b = sP[chunk + h][c4];
            sP[chunk][c4] = make_float4(a.x + b.x, a.y + b.y, a.z + b.z, a.w + b.w);
        }
        __syncthreads();
    }
    if (chunk == 0) *(float4*)&g_pool[g * 64 + c4 * 4] = sP[0][c4];
    if (tid == 0) g_gcnt[g] = (float)(end - start);
}

// ---------------- final: out[g] = ((pool[g]/cnt)@W3 + b3)@Wlin + blin --------------
__global__ void __launch_bounds__(64) final2_kernel(
    const float* __restrict__ W3, const float* __restrict__ b3,
    const float* __restrict__ Wlin, const float* __restrict__ blin,
    float* __restrict__ out)
{
    __shared__ float pooled[64];
    __shared__ float t3[64];
    int g = blockIdx.x;
    int j = threadIdx.x;

    float inv = 1.0f / fmaxf(g_gcnt[g], 1.0f);
    pooled[j] = g_pool[g * 64 + j] * inv;
    __syncthreads();

    float s = b3[j];
    #pragma unroll
    for (int h = 0; h < 64; h++)
        s = fmaf(pooled[h], W3[h * 64 + j], s);
    t3[j] = s;
    __syncthreads();

    if (j < NC) {
        float o = blin[j];
        #pragma unroll
        for (int h = 0; h < 64; h++)
            o = fmaf(t3[h], Wlin[h * NC + j], o);
        out[g * NC + j] = o;
    }
}

// ---------------- launch ----------------
extern "C" void kernel_launch(void* const* d_in, const int* in_sizes, int n_in,
                              void* d_out, int out_size)
{
    const float* x     = (const float*)d_in[0];
    const void*  ei    = d_in[1];
    const void*  batch = d_in[2];
    const float* W1 = (const float*)d_in[3];
    const float* b1 = (const float*)d_in[4];
    const float* W2 = (const float*)d_in[5];
    const float* b2 = (const float*)d_in[6];
    const float* W3 = (const float*)d_in[7];
    const float* b3 = (const float*)d_in[8];
    const float* Wlin = (const float*)d_in[9];
    const float* blin = (const float*)d_in[10];
    float* out = (float*)d_out;

    // Side stream + events (created once on first, non-captured call).
    static cudaStream_t s2 = nullptr;
    static cudaEvent_t evFork = nullptr, evCsr = nullptr, evG1 = nullptr, evJoin = nullptr;
    if (!s2) {
        cudaStreamCreateWithFlags(&s2, cudaStreamNonBlocking);
        cudaEventCreateWithFlags(&evFork, cudaEventDisableTiming);
        cudaEventCreateWithFlags(&evCsr,  cudaEventDisableTiming);
        cudaEventCreateWithFlags(&evG1,   cudaEventDisableTiming);
        cudaEventCreateWithFlags(&evJoin, cudaEventDisableTiming);
    }

    const int eB = (NE + 255) / 256;
    const int gemmB = (NN + TR - 1) / TR;                  // full-grid blocks
    const int gemmB_c0 = HCHUNK / TR;                      // chunk0 blocks (547)
    const int gemmB_c1 = (NN - HCHUNK + TR - 1) / TR;      // chunk1 blocks
    const int gatB_c0 = (HCHUNK * 16 + 255) / 256;
    const int gatB_c1 = ((NN - HCHUNK) * 16 + 255) / 256;
    const int gatB = (NN * 16 + 255) / 256;

    // ---- Phase 1: gemm1 on s2 overlaps CSR build on main stream ----
    cudaEventRecord(evFork, 0);
    cudaStreamWaitEvent(s2, evFork, 0);

    gemm_kernel<<<gemmB, GEMM_T, 0, s2>>>(x, -1, nullptr, W1, 0, 0, NN);   // buf0 = x@W1

    count_kernel<<<eB, 256>>>(ei);
    blocksum_kernel<<<NBLK, 256>>>();
    rowstart_kernel<<<NBLK, 256>>>();
    fill_kernel<<<eB, 256>>>(ei);
    cudaEventRecord(evCsr, 0);                   // CSR ready

    // ---- Phase 2: chunked gather1 / gemm2 pipeline ----
    // main: wait gemm1, gather1 chunk0; s2: wait CSR, gather1 chunk1.
    cudaEventRecord(evJoin, s2);                 // gemm1 done
    cudaStreamWaitEvent(0, evJoin, 0);
    cudaStreamWaitEvent(s2, evCsr, 0);

    gather_kernel<<<gatB_c0, 256>>>(0, 1, 0, HCHUNK);                 // main: buf1[0,H)
    gather_kernel<<<gatB_c1, 256, 0, s2>>>(0, 1, HCHUNK, NN);         // s2:   buf1[H,NN)
    cudaEventRecord(evG1, s2);

    // gemm2 chunk0 overlaps gather1 chunk1
    gemm_kernel<<<gemmB_c0, GEMM_T>>>(nullptr, 1, b1, W2, 0, 0, HCHUNK);
    cudaStreamWaitEvent(0, evG1, 0);
    gemm_kernel<<<gemmB_c1, GEMM_T>>>(nullptr, 1, b1, W2, 0, HCHUNK, NN);

    // ---- Phase 3: serial tail (full-dependency gathers) ----
    gather_kernel<<<gatB, 256>>>(0, 1, 0, NN);           // buf1 = A buf0
    gather_relu_kernel<<<gatB, 256>>>(1, 0, b2);         // buf0 = A relu(buf1+b2)
    pool_kernel<<<NG, 256>>>(0, batch, (const int*)ei);
    final2_kernel<<<NG, 64>>>(W3, b3, Wlin, blin, out);
}

// round 16
// speedup vs baseline: 1.1023x; 1.1023x over previous
#include <cuda_runtime.h>

#define NN 100000
#define NE 1250000
#define HID 64
#define NG 256
#define NC 10
#define NBLK 391         // ceil(NN/256)
#define TCR 128          // rows per tensor-GEMM block
#define TC_SMEM_BYTES (TCR * 68 * 4 + 64 * 72 * 4)   // sA + sW = 53248

typedef unsigned long long ull;

// ---------------- scratch (static device globals; zero-initialized at load) -------
__device__ int   g_cnt_in[NN];
__device__ int   g_fill[NN];
__device__ int   g_rowstart[NN + 1];
__device__ float g_dinv[NN];
__device__ int   g_bsum[NBLK];
__device__ int2  g_csr[NE];           // (src, bitcast(norm)) per edge, grouped by dst
__device__ float g_buf0[NN * HID];
__device__ float g_buf1[NN * HID];
__device__ float g_pool[NG * HID];
__device__ float g_gcnt[NG];

__device__ __forceinline__ float* buf_sel(int which) {
    return (which == 0) ? g_buf0 : g_buf1;
}
__device__ __forceinline__ const float* cbuf_sel(int which) {
    return (which == 0) ? g_buf0 : g_buf1;
}

// Per-warp int64-vs-int32 detection from edge_index.
__device__ __forceinline__ int detect64(const int* __restrict__ ei32) {
    int lane = threadIdx.x & 31;
    int w = ei32[1 + 2 * lane];
    return __all_sync(0xffffffffu, w == 0);
}

__device__ __forceinline__ int ld_idx(const void* p, long long e, int is64) {
    if (is64) return (int)((const long long*)p)[e];
    return ((const int*)p)[e];
}

// ---------------- tf32 helpers ----------------
__device__ __forceinline__ unsigned tf32_of(float x) {
    unsigned r;
    asm("cvt.rna.tf32.f32 %0, %1;" : "=r"(r) : "f"(x));
    return r;
}

// mma.sync m16n8k8 tf32: D += A*B (row.col), acc in-place
__device__ __forceinline__ void mma_tf32(float* c, const unsigned* a, unsigned b0, unsigned b1) {
    asm volatile(
        "mma.sync.aligned.m16n8k8.row.col.f32.tf32.tf32.f32 "
        "{%0,%1,%2,%3}, {%4,%5,%6,%7}, {%8,%9}, {%0,%1,%2,%3};"
        : "+f"(c[0]), "+f"(c[1]), "+f"(c[2]), "+f"(c[3])
        : "r"(a[0]), "r"(a[1]), "r"(a[2]), "r"(a[3]), "r"(b0), "r"(b1));
}

// ---------------- CSR gather for one destination row, 16 threads/row --------------
__device__ __forceinline__ float4 gather_row(const float* __restrict__ in, int i, int c)
{
    int beg = g_rowstart[i];
    int end = g_rowstart[i + 1];
    float di = g_dinv[i];
    float sw = di * di;

    float4 v = *(const float4*)&in[i * 64 + c];
    float4 s0 = make_float4(v.x * sw, v.y * sw, v.z * sw, v.w * sw);
    float4 s1 = make_float4(0.f, 0.f, 0.f, 0.f);

    int e = beg;
    for (; e + 3 < end; e += 4) {
        int2 p0 = g_csr[e];
        int2 p1 = g_csr[e + 1];
        int2 p2 = g_csr[e + 2];
        int2 p3 = g_csr[e + 3];
        float w0 = __int_as_float(p0.y), w1 = __int_as_float(p1.y);
        float w2 = __int_as_float(p2.y), w3 = __int_as_float(p3.y);
        float4 v0 = *(const float4*)&in[p0.x * 64 + c];
        float4 v1 = *(const float4*)&in[p1.x * 64 + c];
        float4 v2 = *(const float4*)&in[p2.x * 64 + c];
        float4 v3 = *(const float4*)&in[p3.x * 64 + c];
        s0.x += v0.x * w0 + v1.x * w1;  s1.x += v2.x * w2 + v3.x * w3;
        s0.y += v0.y * w0 + v1.y * w1;  s1.y += v2.y * w2 + v3.y * w3;
        s0.z += v0.z * w0 + v1.z * w1;  s1.z += v2.z * w2 + v3.z * w3;
        s0.w += v0.w * w0 + v1.w * w1;  s1.w += v2.w * w2 + v3.w * w3;
    }
    for (; e < end; e++) {
        int2 p0 = g_csr[e];
        float w0 = __int_as_float(p0.y);
        float4 v0 = *(const float4*)&in[p0.x * 64 + c];
        s0.x += v0.x * w0; s0.y += v0.y * w0; s0.z += v0.z * w0; s0.w += v0.w * w0;
    }
    return make_float4(s0.x + s1.x, s0.y + s1.y, s0.z + s1.z, s0.w + s1.w);
}

// Same, applying relu(row + bias4) to every loaded row (layer-3 commutation fold).
__device__ __forceinline__ float4 gather_row_relu(const float* __restrict__ in,
                                                  int i, int c, float4 bv)
{
    int beg = g_rowstart[i];
    int end = g_rowstart[i + 1];
    float di = g_dinv[i];
    float sw = di * di;

    float4 v = *(const float4*)&in[i * 64 + c];
    v.x = fmaxf(v.x + bv.x, 0.f); v.y = fmaxf(v.y + bv.y, 0.f);
    v.z = fmaxf(v.z + bv.z, 0.f); v.w = fmaxf(v.w + bv.w, 0.f);
    float4 s0 = make_float4(v.x * sw, v.y * sw, v.z * sw, v.w * sw);

    int e = beg;
    for (; e + 1 < end; e += 2) {
        int2 p0 = g_csr[e];
        int2 p1 = g_csr[e + 1];
        float w0 = __int_as_float(p0.y), w1 = __int_as_float(p1.y);
        float4 v0 = *(const float4*)&in[p0.x * 64 + c];
        float4 v1 = *(const float4*)&in[p1.x * 64 + c];
        v0.x = fmaxf(v0.x + bv.x, 0.f); v0.y = fmaxf(v0.y + bv.y, 0.f);
        v0.z = fmaxf(v0.z + bv.z, 0.f); v0.w = fmaxf(v0.w + bv.w, 0.f);
        v1.x = fmaxf(v1.x + bv.x, 0.f); v1.y = fmaxf(v1.y + bv.y, 0.f);
        v1.z = fmaxf(v1.z + bv.z, 0.f); v1.w = fmaxf(v1.w + bv.w, 0.f);
        s0.x += v0.x * w0 + v1.x * w1;
        s0.y += v0.y * w0 + v1.y * w1;
        s0.z += v0.z * w0 + v1.z * w1;
        s0.w += v0.w * w0 + v1.w * w1;
    }
    if (e < end) {
        int2 p0 = g_csr[e];
        float w0 = __int_as_float(p0.y);
        float4 v0 = *(const float4*)&in[p0.x * 64 + c];
        v0.x = fmaxf(v0.x + bv.x, 0.f); v0.y = fmaxf(v0.y + bv.y, 0.f);
        v0.z = fmaxf(v0.z + bv.z, 0.f); v0.w = fmaxf(v0.w + bv.w, 0.f);
        s0.x += v0.x * w0; s0.y += v0.y * w0; s0.z += v0.z * w0; s0.w += v0.w * w0;
    }
    return s0;
}

// ---------------- preprocessing ----------------
__global__ void count_kernel(const void* __restrict__ ei) {
    int is64 = detect64((const int*)ei);
    int e = blockIdx.x * blockDim.x + threadIdx.x;
    if (e >= NE) return;
    atomicAdd(&g_cnt_in[ld_idx(ei, (long long)NE + e, is64)], 1);
}

__global__ void blocksum_kernel() {
    __shared__ int sred[256];
    int i = blockIdx.x * 256 + threadIdx.x;
    int v = (i < NN) ? g_cnt_in[i] : 0;
    if (i < NN) g_dinv[i] = rsqrtf((float)v + 1.0f);
    sred[threadIdx.x] = v;
    __syncthreads();
    for (int h = 128; h > 0; h >>= 1) {
        if (threadIdx.x < h) sred[threadIdx.x] += sred[threadIdx.x + h];
        __syncthreads();
    }
    if (threadIdx.x == 0) g_bsum[blockIdx.x] = sred[0];
}

__global__ void rowstart_kernel() {
    __shared__ int s[256];
    int t = threadIdx.x;

    int pre = 0;
    for (int j = t; j < blockIdx.x; j += 256) pre += g_bsum[j];
    s[t] = pre;
    __syncthreads();
    for (int h = 128; h > 0; h >>= 1) {
        if (t < h) s[t] += s[t + h];
        __syncthreads();
    }
    int base = s[0];
    __syncthreads();

    int i = blockIdx.x * 256 + t;
    int own = (i < NN) ? g_cnt_in[i] : 0;
    s[t] = own;
    __syncthreads();
    for (int off = 1; off < 256; off <<= 1) {
        int v = (t >= off) ? s[t - off] : 0;
        __syncthreads();
        s[t] += v;
        __syncthreads();
    }
    if (i < NN) {
        g_rowstart[i] = base + s[t] - own;
        g_fill[i] = 0;
        g_cnt_in[i] = 0;
    }
    if (i == 0) g_rowstart[NN] = NE;
}

__global__ void fill_kernel(const void* __restrict__ ei) {
    int is64 = detect64((const int*)ei);
    int e = blockIdx.x * blockDim.x + threadIdx.x;
    if (e >= NE) return;
    int s = ld_idx(ei, e, is64);
    int d = ld_idx(ei, (long long)NE + e, is64);
    int pos = g_rowstart[d] + atomicAdd(&g_fill[d], 1);
    float w = g_dinv[s] * g_dinv[d];
    g_csr[pos] = make_int2(s, __float_as_int(w));
}

// ---------------- tensor-core GEMM: out_sel = act(in (+bias)) @ W -----------------
// 128 rows x 64 cols per block, 8 warps; warp w owns rows [w*16, w*16+16).
// 3xTF32: a=ah+al, w=wh+wl; acc += ah*wh + al*wh + ah*wl (residual ~2^-22).
__global__ void __launch_bounds__(256) gemm_tc_kernel(
    const float* __restrict__ in_ext, int in_sel,
    const float* __restrict__ bias,
    const float* __restrict__ W, int out_sel, int row_base, int row_end)
{
    extern __shared__ float smem[];
    float* sA = smem;                  // [r][k], stride 68 (A-frag conflict-free)
    float* sW = smem + TCR * 68;       // [k][j], stride 72 (B-frag conflict-free)

    const float* in = in_ext ? in_ext : cbuf_sel(in_sel);
    float* out = buf_sel(out_sel);

    int tid = threadIdx.x;
    int r0 = row_base + blockIdx.x * TCR;
    const bool has_bias = (bias != nullptr);

    // stage W [64][64] -> sW stride 72
    for (int q = tid; q < 64 * 16; q += 256) {
        int kk = q >> 4, j4 = q & 15;
        float4 w = *(const float4*)&W[kk * 64 + j4 * 4];
        *(float4*)&sW[kk * 72 + j4 * 4] = w;
    }
    // stage A rows (bias+relu fused) -> sA stride 68
    for (int q = tid; q < TCR * 16; q += 256) {
        int r = q >> 4, k4 = q & 15;
        int gr = r0 + r;
        float4 v = make_float4(0.f, 0.f, 0.f, 0.f);
        if (gr < row_end) {
            v = *(const float4*)&in[gr * 64 + k4 * 4];
            if (has_bias) {
                v.x = fmaxf(v.x + bias[k4 * 4 + 0], 0.f);
                v.y = fmaxf(v.y + bias[k4 * 4 + 1], 0.f);
                v.z = fmaxf(v.z + bias[k4 * 4 + 2], 0.f);
                v.w = fmaxf(v.w + bias[k4 * 4 + 3], 0.f);
            }
        }
        *(float4*)&sA[r * 68 + k4 * 4] = v;
    }
    __syncthreads();

    int warp = tid >> 5;
    int lane = tid & 31;
    int g = lane >> 2;        // group 0..7
    int tg = lane & 3;        // thread-in-group 0..3
    int rw = warp * 16;       // warp row offset within tile

    float acc[8][4];
    #pragma unroll
    for (int nt = 0; nt < 8; nt++)
        #pragma unroll
        for (int i = 0; i < 4; i++) acc[nt][i] = 0.f;

    #pragma unroll
    for (int kk = 0; kk < 8; kk++) {
        int kb = kk * 8;
        // A fragments (m16k8): hi + lo
        float af[4];
        af[0] = sA[(rw + g) * 68 + kb + tg];
        af[1] = sA[(rw + g + 8) * 68 + kb + tg];
        af[2] = sA[(rw + g) * 68 + kb + tg + 4];
        af[3] = sA[(rw + g + 8) * 68 + kb + tg + 4];
        unsigned ah[4], al[4];
        #pragma unroll
        for (int i = 0; i < 4; i++) {
            ah[i] = tf32_of(af[i]);
            al[i] = tf32_of(af[i] - __uint_as_float(ah[i]));
        }
        #pragma unroll
        for (int nt = 0; nt < 8; nt++) {
            int n0 = nt * 8;
            float bf0 = sW[(kb + tg) * 72 + n0 + g];
            float bf1 = sW[(kb + tg + 4) * 72 + n0 + g];
            unsigned bh0 = tf32_of(bf0);
            unsigned bl0 = tf32_of(bf0 - __uint_as_float(bh0));
            unsigned bh1 = tf32_of(bf1);
            unsigned bl1 = tf32_of(bf1 - __uint_as_float(bh1));
            mma_tf32(acc[nt], ah, bh0, bh1);
            mma_tf32(acc[nt], al, bh0, bh1);
            mma_tf32(acc[nt], ah, bl0, bl1);
        }
    }

    // store: c0/c1 -> out[r0+rw+g][n0+2tg..+1], c2/c3 -> row +8
    int ra = r0 + rw + g;
    int rb = ra + 8;
    #pragma unroll
    for (int nt = 0; nt < 8; nt++) {
        int j = nt * 8 + 2 * tg;
        if (ra < row_end) *(float2*)&out[ra * 64 + j] = make_float2(acc[nt][0], acc[nt][1]);
        if (rb < row_end) *(float2*)&out[rb * 64 + j] = make_float2(acc[nt][2], acc[nt][3]);
    }
}

// ---------------- standalone gather over node range [node_base, node_end) ---------
__global__ void __launch_bounds__(256) gather_kernel(int in_sel, int out_sel,
                                                     int node_base, int node_end)
{
    const float* in = cbuf_sel(in_sel);
    float* acc_out = buf_sel(out_sel);

    int t = blockIdx.x * blockDim.x + threadIdx.x;
    int i = node_base + (t >> 4);
    if (i >= node_end) return;
    int c = (t & 15) << 2;

    float4 s = gather_row(in, i, c);
    *(float4*)&acc_out[i * 64 + c] = s;
}

// ---------------- gather of relu(in + b) ----------------
__global__ void __launch_bounds__(256) gather_relu_kernel(
    int in_sel, int out_sel, const float* __restrict__ bias)
{
    const float* in = cbuf_sel(in_sel);
    float* acc_out = buf_sel(out_sel);

    int t = blockIdx.x * blockDim.x + threadIdx.x;
    int i = t >> 4;
    if (i >= NN) return;
    int c = (t & 15) << 2;
    float4 bv = *(const float4*)&bias[c];

    float4 s = gather_row_relu(in, i, c, bv);
    *(float4*)&acc_out[i * 64 + c] = s;
}

// ---------------- segmented mean pool (batch is sorted; no atomics) ----------------
__global__ void __launch_bounds__(256) pool_kernel(
    int in_sel, const void* __restrict__ batch, const int* __restrict__ ei32)
{
    __shared__ float4 sP[16][16];
    const float* acc = cbuf_sel(in_sel);
    int is64 = detect64(ei32);
    int g = blockIdx.x;
    int tid = threadIdx.x;
    int chunk = tid >> 4;
    int c4 = tid & 15;

    int lo = 0, hi = NN;
    while (lo < hi) { int mid = (lo + hi) >> 1; if (ld_idx(batch, mid, is64) < g) lo = mid + 1; else hi = mid; }
    int start = lo;
    lo = start; hi = NN;
    while (lo < hi) { int mid = (lo + hi) >> 1; if (ld_idx(batch, mid, is64) < g + 1) lo = mid + 1; else hi = mid; }
    int end = lo;

    float4 sum = make_float4(0.f, 0.f, 0.f, 0.f);
    for (int n = start + chunk; n < end; n += 16) {
        float4 v = *(const float4*)&acc[n * 64 + c4 * 4];
        sum.x += v.x; sum.y += v.y; sum.z += v.z; sum.w += v.w;
    }
    sP[chunk][c4] = sum;
    __syncthreads();
    for (int h = 8; h > 0; h >>= 1) {
        if (chunk < h) {
            float4 a = sP[chunk][c4], b = sP[chunk + h][c4];
            sP[chunk][c4] = make_float4(a.x + b.x, a.y + b.y, a.z + b.z, a.w + b.w);
        }
        __syncthreads();
    }
    if (chunk == 0) *(float4*)&g_pool[g * 64 + c4 * 4] = sP[0][c4];
    if (tid == 0) g_gcnt[g] = (float)(end - start);
}

// ---------------- final: out[g] = ((pool[g]/cnt)@W3 + b3)@Wlin + blin --------------
__global__ void __launch_bounds__(64) final2_kernel(
    const float* __restrict__ W3, const float* __restrict__ b3,
    const float* __restrict__ Wlin, const float* __restrict__ blin,
    float* __restrict__ out)
{
    __shared__ float pooled[64];
    __shared__ float t3[64];
    int g = blockIdx.x;
    int j = threadIdx.x;

    float inv = 1.0f / fmaxf(g_gcnt[g], 1.0f);
    pooled[j] = g_pool[g * 64 + j] * inv;
    __syncthreads();

    float s = b3[j];
    #pragma unroll
    for (int h = 0; h < 64; h++)
        s = fmaf(pooled[h], W3[h * 64 + j], s);
    t3[j] = s;
    __syncthreads();

    if (j < NC) {
        float o = blin[j];
        #pragma unroll
        for (int h = 0; h < 64; h++)
            o = fmaf(t3[h], Wlin[h * NC + j], o);
        out[g * NC + j] = o;
    }
}

// ---------------- launch ----------------
extern "C" void kernel_launch(void* const* d_in, const int* in_sizes, int n_in,
                              void* d_out, int out_size)
{
    const float* x     = (const float*)d_in[0];
    const void*  ei    = d_in[1];
    const void*  batch = d_in[2];
    const float* W1 = (const float*)d_in[3];
    const float* b1 = (const float*)d_in[4];
    const float* W2 = (const float*)d_in[5];
    const float* b2 = (const float*)d_in[6];
    const float* W3 = (const float*)d_in[7];
    const float* b3 = (const float*)d_in[8];
    const float* Wlin = (const float*)d_in[9];
    const float* blin = (const float*)d_in[10];
    float* out = (float*)d_out;

    static cudaStream_t s2 = nullptr;
    static cudaEvent_t evFork = nullptr, evJoin = nullptr;
    if (!s2) {
        cudaStreamCreateWithFlags(&s2, cudaStreamNonBlocking);
        cudaEventCreateWithFlags(&evFork, cudaEventDisableTiming);
        cudaEventCreateWithFlags(&evJoin, cudaEventDisableTiming);
        cudaFuncSetAttribute(gemm_tc_kernel,
                             cudaFuncAttributeMaxDynamicSharedMemorySize, TC_SMEM_BYTES);
    }

    const int eB = (NE + 255) / 256;
    const int tcB = (NN + TCR - 1) / TCR;            // 782
    const int gatB = (NN * 16 + 255) / 256;

    // Phase 1: gemm1 (tensor core) on s2 overlaps CSR build on main stream.
    cudaEventRecord(evFork, 0);
    cudaStreamWaitEvent(s2, evFork, 0);

    gemm_tc_kernel<<<tcB, 256, TC_SMEM_BYTES, s2>>>(x, -1, nullptr, W1, 0, 0, NN);
    cudaEventRecord(evJoin, s2);

    count_kernel<<<eB, 256>>>(ei);
    blocksum_kernel<<<NBLK, 256>>>();
    rowstart_kernel<<<NBLK, 256>>>();
    fill_kernel<<<eB, 256>>>(ei);

    cudaStreamWaitEvent(0, evJoin, 0);               // join: gather needs buf0 + CSR

    // Phase 2: serial hot path.
    gather_kernel<<<gatB, 256>>>(0, 1, 0, NN);                        // buf1 = A buf0
    gemm_tc_kernel<<<tcB, 256, TC_SMEM_BYTES>>>(nullptr, 1, b1, W2, 0, 0, NN);
    gather_kernel<<<gatB, 256>>>(0, 1, 0, NN);                        // buf1 = A buf0
    gather_relu_kernel<<<gatB, 256>>>(1, 0, b2);                      // buf0 = A relu(buf1+b2)
    pool_kernel<<<NG, 256>>>(0, batch, (const int*)ei);
    final2_kernel<<<NG, 64>>>(W3, b3, Wlin, blin, out);
}

// round 17
// speedup vs baseline: 1.1909x; 1.0804x over previous
#include <cuda_runtime.h>

#define NN 100000
#define NE 1250000
#define HID 64
#define NG 256
#define NC 10
#define NBLK 391         // ceil(NN/256)
#define TCR 128          // rows per tensor-GEMM block
#define APITCH 36        // k2-pitch of A planes (bank: 4g+tg bijective)
#define WPITCH 72        // j-pitch of W planes (bank: 8tg+g bijective)
// dynamic smem: uAh[128*36] uAl[128*36] uWh[32*72] uWl[32*72] (unsigned) = 55296 B
#define TC_SMEM_WORDS (2 * TCR * APITCH + 2 * 32 * WPITCH)
#define TC_SMEM_BYTES (TC_SMEM_WORDS * 4)

typedef unsigned long long ull;

// ---------------- scratch (static device globals; zero-initialized at load) -------
__device__ int   g_cnt_in[NN];
__device__ int   g_fill[NN];
__device__ int   g_rowstart[NN + 1];
__device__ float g_dinv[NN];
__device__ int   g_bsum[NBLK];
__device__ int2  g_csr[NE];           // (src, bitcast(norm)) per edge, grouped by dst
__device__ float g_buf0[NN * HID];
__device__ float g_buf1[NN * HID];
__device__ float g_pool[NG * HID];
__device__ float g_gcnt[NG];

__device__ __forceinline__ float* buf_sel(int which) {
    return (which == 0) ? g_buf0 : g_buf1;
}
__device__ __forceinline__ const float* cbuf_sel(int which) {
    return (which == 0) ? g_buf0 : g_buf1;
}

// Per-warp int64-vs-int32 detection from edge_index.
__device__ __forceinline__ int detect64(const int* __restrict__ ei32) {
    int lane = threadIdx.x & 31;
    int w = ei32[1 + 2 * lane];
    return __all_sync(0xffffffffu, w == 0);
}

__device__ __forceinline__ int ld_idx(const void* p, long long e, int is64) {
    if (is64) return (int)((const long long*)p)[e];
    return ((const int*)p)[e];
}

// ---------------- bf16 helpers ----------------
// pack two floats into bf16x2: low 16 bits = lo (even k), high = hi (odd k)
__device__ __forceinline__ unsigned pack_bf16(float lo, float hi) {
    unsigned r;
    asm("cvt.rn.bf16x2.f32 %0, %1, %2;" : "=r"(r) : "f"(hi), "f"(lo));
    return r;
}
__device__ __forceinline__ float bf_lo(unsigned u) { return __uint_as_float(u << 16); }
__device__ __forceinline__ float bf_hi(unsigned u) { return __uint_as_float(u & 0xFFFF0000u); }

// mma.sync m16n8k16 bf16: D += A*B (row.col), acc in-place
__device__ __forceinline__ void mma_bf16(float* c, const unsigned* a, unsigned b0, unsigned b1) {
    asm volatile(
        "mma.sync.aligned.m16n8k16.row.col.f32.bf16.bf16.f32 "
        "{%0,%1,%2,%3}, {%4,%5,%6,%7}, {%8,%9}, {%0,%1,%2,%3};"
        : "+f"(c[0]), "+f"(c[1]), "+f"(c[2]), "+f"(c[3])
        : "r"(a[0]), "r"(a[1]), "r"(a[2]), "r"(a[3]), "r"(b0), "r"(b1));
}

// ---------------- CSR gather for one destination row, 16 threads/row --------------
__device__ __forceinline__ float4 gather_row(const float* __restrict__ in, int i, int c)
{
    int beg = g_rowstart[i];
    int end = g_rowstart[i + 1];
    float di = g_dinv[i];
    float sw = di * di;

    float4 v = *(const float4*)&in[i * 64 + c];
    float4 s0 = make_float4(v.x * sw, v.y * sw, v.z * sw, v.w * sw);
    float4 s1 = make_float4(0.f, 0.f, 0.f, 0.f);

    int e = beg;
    for (; e + 3 < end; e += 4) {
        int2 p0 = g_csr[e];
        int2 p1 = g_csr[e + 1];
        int2 p2 = g_csr[e + 2];
        int2 p3 = g_csr[e + 3];
        float w0 = __int_as_float(p0.y), w1 = __int_as_float(p1.y);
        float w2 = __int_as_float(p2.y), w3 = __int_as_float(p3.y);
        float4 v0 = *(const float4*)&in[p0.x * 64 + c];
        float4 v1 = *(const float4*)&in[p1.x * 64 + c];
        float4 v2 = *(const float4*)&in[p2.x * 64 + c];
        float4 v3 = *(const float4*)&in[p3.x * 64 + c];
        s0.x += v0.x * w0 + v1.x * w1;  s1.x += v2.x * w2 + v3.x * w3;
        s0.y += v0.y * w0 + v1.y * w1;  s1.y += v2.y * w2 + v3.y * w3;
        s0.z += v0.z * w0 + v1.z * w1;  s1.z += v2.z * w2 + v3.z * w3;
        s0.w += v0.w * w0 + v1.w * w1;  s1.w += v2.w * w2 + v3.w * w3;
    }
    for (; e < end; e++) {
        int2 p0 = g_csr[e];
        float w0 = __int_as_float(p0.y);
        float4 v0 = *(const float4*)&in[p0.x * 64 + c];
        s0.x += v0.x * w0; s0.y += v0.y * w0; s0.z += v0.z * w0; s0.w += v0.w * w0;
    }
    return make_float4(s0.x + s1.x, s0.y + s1.y, s0.z + s1.z, s0.w + s1.w);
}

// ---------------- preprocessing ----------------
__global__ void count_kernel(const void* __restrict__ ei) {
    int is64 = detect64((const int*)ei);
    int e = blockIdx.x * blockDim.x + threadIdx.x;
    if (e >= NE) return;
    atomicAdd(&g_cnt_in[ld_idx(ei, (long long)NE + e, is64)], 1);
}

__global__ void blocksum_kernel() {
    __shared__ int sred[256];
    int i = blockIdx.x * 256 + threadIdx.x;
    int v = (i < NN) ? g_cnt_in[i] : 0;
    if (i < NN) g_dinv[i] = rsqrtf((float)v + 1.0f);
    sred[threadIdx.x] = v;
    __syncthreads();
    for (int h = 128; h > 0; h >>= 1) {
        if (threadIdx.x < h) sred[threadIdx.x] += sred[threadIdx.x + h];
        __syncthreads();
    }
    if (threadIdx.x == 0) g_bsum[blockIdx.x] = sred[0];
}

__global__ void rowstart_kernel() {
    __shared__ int s[256];
    int t = threadIdx.x;

    int pre = 0;
    for (int j = t; j < blockIdx.x; j += 256) pre += g_bsum[j];
    s[t] = pre;
    __syncthreads();
    for (int h = 128; h > 0; h >>= 1) {
        if (t < h) s[t] += s[t + h];
        __syncthreads();
    }
    int base = s[0];
    __syncthreads();

    int i = blockIdx.x * 256 + t;
    int own = (i < NN) ? g_cnt_in[i] : 0;
    s[t] = own;
    __syncthreads();
    for (int off = 1; off < 256; off <<= 1) {
        int v = (t >= off) ? s[t - off] : 0;
        __syncthreads();
        s[t] += v;
        __syncthreads();
    }
    if (i < NN) {
        g_rowstart[i] = base + s[t] - own;
        g_fill[i] = 0;
        g_cnt_in[i] = 0;
    }
    if (i == 0) g_rowstart[NN] = NE;
}

__global__ void fill_kernel(const void* __restrict__ ei) {
    int is64 = detect64((const int*)ei);
    int e = blockIdx.x * blockDim.x + threadIdx.x;
    if (e >= NE) return;
    int s = ld_idx(ei, e, is64);
    int d = ld_idx(ei, (long long)NE + e, is64);
    int pos = g_rowstart[d] + atomicAdd(&g_fill[d], 1);
    float w = g_dinv[s] * g_dinv[d];
    g_csr[pos] = make_int2(s, __float_as_int(w));
}

// ---------------- tensor-core GEMM (bf16 3-term split, m16n8k16) ------------------
// 128 rows x 64 cols per block, 8 warps. All cvts in staging; mainloop = LDS+MMA.
__global__ void __launch_bounds__(256) gemm_tc_kernel(
    const float* __restrict__ in_ext, int in_sel,
    const float* __restrict__ bias,
    const float* __restrict__ W, int out_sel, int row_base, int row_end)
{
    extern __shared__ unsigned usmem[];
    unsigned* uAh = usmem;                          // [r][k2] pitch 36
    unsigned* uAl = uAh + TCR * APITCH;
    unsigned* uWh = uAl + TCR * APITCH;             // [k2][j] pitch 72
    unsigned* uWl = uWh + 32 * WPITCH;

    const float* in = in_ext ? in_ext : cbuf_sel(in_sel);
    float* out = buf_sel(out_sel);

    int tid = threadIdx.x;
    int r0 = row_base + blockIdx.x * TCR;
    const bool has_bias = (bias != nullptr);

    // stage W: pack k-adjacent row pairs per column, hi+lo planes
    for (int q = tid; q < 32 * 16; q += 256) {
        int k2 = q >> 4, j4 = q & 15;
        float4 f0 = *(const float4*)&W[(2 * k2) * 64 + j4 * 4];
        float4 f1 = *(const float4*)&W[(2 * k2 + 1) * 64 + j4 * 4];
        int o = k2 * WPITCH + j4 * 4;
        unsigned h0 = pack_bf16(f0.x, f1.x);
        unsigned h1 = pack_bf16(f0.y, f1.y);
        unsigned h2 = pack_bf16(f0.z, f1.z);
        unsigned h3 = pack_bf16(f0.w, f1.w);
        uWh[o + 0] = h0; uWh[o + 1] = h1; uWh[o + 2] = h2; uWh[o + 3] = h3;
        uWl[o + 0] = pack_bf16(f0.x - bf_lo(h0), f1.x - bf_hi(h0));
        uWl[o + 1] = pack_bf16(f0.y - bf_lo(h1), f1.y - bf_hi(h1));
        uWl[o + 2] = pack_bf16(f0.z - bf_lo(h2), f1.z - bf_hi(h2));
        uWl[o + 3] = pack_bf16(f0.w - bf_lo(h3), f1.w - bf_hi(h3));
    }
    // stage A rows (bias+relu fused): pack k pairs, hi+lo planes
    for (int q = tid; q < TCR * 16; q += 256) {
        int r = q >> 4, k4 = q & 15;
        int gr = r0 + r;
        float4 v = make_float4(0.f, 0.f, 0.f, 0.f);
        if (gr < row_end) {
            v = *(const float4*)&in[gr * 64 + k4 * 4];
            if (has_bias) {
                v.x = fmaxf(v.x + bias[k4 * 4 + 0], 0.f);
                v.y = fmaxf(v.y + bias[k4 * 4 + 1], 0.f);
                v.z = fmaxf(v.z + bias[k4 * 4 + 2], 0.f);
                v.w = fmaxf(v.w + bias[k4 * 4 + 3], 0.f);
            }
        }
        int o = r * APITCH + k4 * 2;
        unsigned h0 = pack_bf16(v.x, v.y);
        unsigned h1 = pack_bf16(v.z, v.w);
        uAh[o + 0] = h0; uAh[o + 1] = h1;
        uAl[o + 0] = pack_bf16(v.x - bf_lo(h0), v.y - bf_hi(h0));
        uAl[o + 1] = pack_bf16(v.z - bf_lo(h1), v.w - bf_hi(h1));
    }
    __syncthreads();

    int warp = tid >> 5;
    int lane = tid & 31;
    int g = lane >> 2;        // 0..7
    int tg = lane & 3;        // 0..3
    int rw = warp * 16;

    float acc[8][4];
    #pragma unroll
    for (int nt = 0; nt < 8; nt++)
        #pragma unroll
        for (int i = 0; i < 4; i++) acc[nt][i] = 0.f;

    #pragma unroll
    for (int kk = 0; kk < 4; kk++) {
        int k2b = kk * 8;
        unsigned ah[4], al[4];
        ah[0] = uAh[(rw + g) * APITCH + k2b + tg];
        ah[1] = uAh[(rw + g + 8) * APITCH + k2b + tg];
        ah[2] = uAh[(rw + g) * APITCH + k2b + tg + 4];
        ah[3] = uAh[(rw + g + 8) * APITCH + k2b + tg + 4];
        al[0] = uAl[(rw + g) * APITCH + k2b + tg];
        al[1] = uAl[(rw + g + 8) * APITCH + k2b + tg];
        al[2] = uAl[(rw + g) * APITCH + k2b + tg + 4];
        al[3] = uAl[(rw + g + 8) * APITCH + k2b + tg + 4];
        #pragma unroll
        for (int nt = 0; nt < 8; nt++) {
            int n0 = nt * 8;
            unsigned bh0 = uWh[(k2b + tg) * WPITCH + n0 + g];
            unsigned bh1 = uWh[(k2b + tg + 4) * WPITCH + n0 + g];
            unsigned bl0 = uWl[(k2b + tg) * WPITCH + n0 + g];
            unsigned bl1 = uWl[(k2b + tg + 4) * WPITCH + n0 + g];
            mma_bf16(acc[nt], ah, bh0, bh1);   // ah*wh
            mma_bf16(acc[nt], al, bh0, bh1);   // al*wh
            mma_bf16(acc[nt], ah, bl0, bl1);   // ah*wl
        }
    }

    int ra = r0 + rw + g;
    int rb = ra + 8;
    #pragma unroll
    for (int nt = 0; nt < 8; nt++) {
        int j = nt * 8 + 2 * tg;
        if (ra < row_end) *(float2*)&out[ra * 64 + j] = make_float2(acc[nt][0], acc[nt][1]);
        if (rb < row_end) *(float2*)&out[rb * 64 + j] = make_float2(acc[nt][2], acc[nt][3]);
    }
}

// ---------------- standalone gather: out = A_hat in ----------------
__global__ void __launch_bounds__(256) gather_kernel(int in_sel, int out_sel)
{
    const float* in = cbuf_sel(in_sel);
    float* acc_out = buf_sel(out_sel);

    int t = blockIdx.x * blockDim.x + threadIdx.x;
    int i = t >> 4;
    if (i >= NN) return;
    int c = (t & 15) << 2;

    float4 s = gather_row(in, i, c);
    *(float4*)&acc_out[i * 64 + c] = s;
}

// ---------------- gather with relu(s + b) applied at STORE (h2 materialization) ---
__global__ void __launch_bounds__(256) gather_store_relu_kernel(
    int in_sel, int out_sel, const float* __restrict__ bias)
{
    const float* in = cbuf_sel(in_sel);
    float* acc_out = buf_sel(out_sel);

    int t = blockIdx.x * blockDim.x + threadIdx.x;
    int i = t >> 4;
    if (i >= NN) return;
    int c = (t & 15) << 2;
    float4 bv = *(const float4*)&bias[c];

    float4 s = gather_row(in, i, c);
    s.x = fmaxf(s.x + bv.x, 0.f);
    s.y = fmaxf(s.y + bv.y, 0.f);
    s.z = fmaxf(s.z + bv.z, 0.f);
    s.w = fmaxf(s.w + bv.w, 0.f);
    *(float4*)&acc_out[i * 64 + c] = s;
}

// ---------------- segmented mean pool (batch is sorted; no atomics) ----------------
__global__ void __launch_bounds__(256) pool_kernel(
    int in_sel, const void* __restrict__ batch, const int* __restrict__ ei32)
{
    __shared__ float4 sP[16][16];
    const float* acc = cbuf_sel(in_sel);
    int is64 = detect64(ei32);
    int g = blockIdx.x;
    int tid = threadIdx.x;
    int chunk = tid >> 4;
    int c4 = tid & 15;

    int lo = 0, hi = NN;
    while (lo < hi) { int mid = (lo + hi) >> 1; if (ld_idx(batch, mid, is64) < g) lo = mid + 1; else hi = mid; }
    int start = lo;
    lo = start; hi = NN;
    while (lo < hi) { int mid = (lo + hi) >> 1; if (ld_idx(batch, mid, is64) < g + 1) lo = mid + 1; else hi = mid; }
    int end = lo;

    float4 sum = make_float4(0.f, 0.f, 0.f, 0.f);
    for (int n = start + chunk; n < end; n += 16) {
        float4 v = *(const float4*)&acc[n * 64 + c4 * 4];
        sum.x += v.x; sum.y += v.y; sum.z += v.z; sum.w += v.w;
    }
    sP[chunk][c4] = sum;
    __syncthreads();
    for (int h = 8; h > 0; h >>= 1) {
        if (chunk < h) {
            float4 a = sP[chunk][c4], b = sP[chunk + h][c4];
            sP[chunk][c4] = make_float4(a.x + b.x, a.y + b.y, a.z + b.z, a.w + b.w);
        }
        __syncthreads();
    }
    if (chunk == 0) *(float4*)&g_pool[g * 64 + c4 * 4] = sP[0][c4];
    if (tid == 0) g_gcnt[g] = (float)(end - start);
}

// ---------------- final: out[g] = ((pool[g]/cnt)@W3 + b3)@Wlin + blin --------------
__global__ void __launch_bounds__(64) final2_kernel(
    const float* __restrict__ W3, const float* __restrict__ b3,
    const float* __restrict__ Wlin, const float* __restrict__ blin,
    float* __restrict__ out)
{
    __shared__ float pooled[64];
    __shared__ float t3[64];
    int g = blockIdx.x;
    int j = threadIdx.x;

    float inv = 1.0f / fmaxf(g_gcnt[g], 1.0f);
    pooled[j] = g_pool[g * 64 + j] * inv;
    __syncthreads();

    float s = b3[j];
    #pragma unroll
    for (int h = 0; h < 64; h++)
        s = fmaf(pooled[h], W3[h * 64 + j], s);
    t3[j] = s;
    __syncthreads();

    if (j < NC) {
        float o = blin[j];
        #pragma unroll
        for (int h = 0; h < 64; h++)
            o = fmaf(t3[h], Wlin[h * NC + j], o);
        out[g * NC + j] = o;
    }
}

// ---------------- launch ----------------
extern "C" void kernel_launch(void* const* d_in, const int* in_sizes, int n_in,
                              void* d_out, int out_size)
{
    const float* x     = (const float*)d_in[0];
    const void*  ei    = d_in[1];
    const void*  batch = d_in[2];
    const float* W1 = (const float*)d_in[3];
    const float* b1 = (const float*)d_in[4];
    const float* W2 = (const float*)d_in[5];
    const float* b2 = (const float*)d_in[6];
    const float* W3 = (const float*)d_in[7];
    const float* b3 = (const float*)d_in[8];
    const float* Wlin = (const float*)d_in[9];
    const float* blin = (const float*)d_in[10];
    float* out = (float*)d_out;

    static cudaStream_t s2 = nullptr;
    static cudaEvent_t evFork = nullptr, evJoin = nullptr;
    if (!s2) {
        cudaStreamCreateWithFlags(&s2, cudaStreamNonBlocking);
        cudaEventCreateWithFlags(&evFork, cudaEventDisableTiming);
        cudaEventCreateWithFlags(&evJoin, cudaEventDisableTiming);
        cudaFuncSetAttribute(gemm_tc_kernel,
                             cudaFuncAttributeMaxDynamicSharedMemorySize, TC_SMEM_BYTES);
    }

    const int eB = (NE + 255) / 256;
    const int tcB = (NN + TCR - 1) / TCR;            // 782
    const int gatB = (NN * 16 + 255) / 256;

    // Phase 1: gemm1 (bf16 tensor core) on s2 overlaps CSR build on main stream.
    cudaEventRecord(evFork, 0);
    cudaStreamWaitEvent(s2, evFork, 0);

    gemm_tc_kernel<<<tcB, 256, TC_SMEM_BYTES, s2>>>(x, -1, nullptr, W1, 0, 0, NN);
    cudaEventRecord(evJoin, s2);

    count_kernel<<<eB, 256>>>(ei);
    blocksum_kernel<<<NBLK, 256>>>();
    rowstart_kernel<<<NBLK, 256>>>();
    fill_kernel<<<eB, 256>>>(ei);

    cudaStreamWaitEvent(0, evJoin, 0);               // join: gather needs buf0 + CSR

    // Phase 2: serial hot path.
    gather_kernel<<<gatB, 256>>>(0, 1);                                       // buf1 = A buf0
    gemm_tc_kernel<<<tcB, 256, TC_SMEM_BYTES>>>(nullptr, 1, b1, W2, 0, 0, NN); // buf0 = relu(buf1+b1)@W2
    gather_store_relu_kernel<<<gatB, 256>>>(0, 1, b2);                        // buf1 = relu(A buf0 + b2) = h2
    gather_kernel<<<gatB, 256>>>(1, 0);                                       // buf0 = A h2
    pool_kernel<<<NG, 256>>>(0, batch, (const int*)ei);
    final2_kernel<<<NG, 64>>>(W3, b3, Wlin, blin, out);
}